// round 13
// baseline (speedup 1.0000x reference)
#include <cuda_runtime.h>
#include <cuda_bf16.h>

// ---------------------------------------------------------------------------
// CausalMLA — fp32, folded V/output paths, register-tiled compress,
// 2-query-per-thread single-wave flash attention.
//   B=2, L=2048, D=2048, H=16, HD=128, LD=32
// ---------------------------------------------------------------------------

#define NTOK   4096
#define DMODEL 2048
#define NHEAD  16
#define HDIM   128
#define LDIM   32
#define SEQ    2048
#define NBH    32
#define CDIM   512      // NHEAD * LDIM

// Scratch (static device globals; no runtime allocation allowed)
__device__ float g_Q  [NTOK * DMODEL];
__device__ float g_K  [NTOK * DMODEL];
__device__ float g_qc [NBH * SEQ * LDIM];
__device__ float g_kc [NBH * SEQ * LDIM];
__device__ float g_vc2[NTOK * CDIM];     // [t, h*32+e]
__device__ float g_ac2[NTOK * CDIM];     // [t, h*32+e]
__device__ float g_WvE[DMODEL * CDIM];   // [d, h*32+e]
__device__ float g_WoE[CDIM * DMODEL];   // [h*32+e, n]
__device__ float g_bvE[CDIM];
__device__ float g_boE[DMODEL];
__device__ float g_boP[32 * DMODEL];     // partial sums for fold_bo

// ---------------------------------------------------------------------------
// Weight folding kernels
// ---------------------------------------------------------------------------
__global__ __launch_bounds__(256) void fold_v_kernel(
    const float* __restrict__ Wv, const float* __restrict__ Wvc,
    float* __restrict__ WvE)
{
    __shared__ float wc[HDIM * LDIM];
    const int tid = threadIdx.x;
    const int h   = blockIdx.x;
    const int d0  = blockIdx.y * 128;
    for (int i = tid; i < HDIM * LDIM; i += 256) wc[i] = Wvc[i];
    __syncthreads();

    #pragma unroll
    for (int i = 0; i < 16; ++i) {
        const int idx = tid + i * 256;
        const int r = idx >> 5, e = idx & 31;
        const float* wrow = Wv + (size_t)(d0 + r) * DMODEL + h * HDIM;
        float acc = 0.f;
        #pragma unroll 8
        for (int dd = 0; dd < HDIM; ++dd)
            acc += wrow[dd] * wc[dd * LDIM + e];
        WvE[(size_t)(d0 + r) * CDIM + h * LDIM + e] = acc;
    }
}

__global__ __launch_bounds__(256) void fold_o_kernel(
    const float* __restrict__ Wd, const float* __restrict__ Wo,
    float* __restrict__ WoE)
{
    __shared__ float wd[LDIM * HDIM];
    const int tid = threadIdx.x;
    const int n0  = blockIdx.x * 128;
    const int h   = blockIdx.y;
    for (int i = tid; i < LDIM * HDIM; i += 256) wd[i] = Wd[i];
    __syncthreads();

    #pragma unroll
    for (int i = 0; i < 16; ++i) {
        const int idx = tid + i * 256;
        const int e = idx >> 7, c = idx & 127;
        float acc = 0.f;
        #pragma unroll 8
        for (int d = 0; d < HDIM; ++d)
            acc += wd[e * HDIM + d] * Wo[(size_t)(h * HDIM + d) * DMODEL + n0 + c];
        WoE[(size_t)(h * LDIM + e) * DMODEL + n0 + c] = acc;
    }
}

__global__ __launch_bounds__(256) void fold_bv_kernel(
    const float* __restrict__ bv, const float* __restrict__ Wvc,
    const float* __restrict__ bvc, float* __restrict__ bvE)
{
    const int i = blockIdx.x * 256 + threadIdx.x;
    if (i >= CDIM) return;
    const int h = i >> 5, e = i & 31;
    float acc = bvc[e];
    for (int dd = 0; dd < HDIM; ++dd)
        acc += bv[h * HDIM + dd] * Wvc[dd * LDIM + e];
    bvE[i] = acc;
}

// fold_bo, stage 1: partial sums over 64-row m slabs (coalesced, 256 blocks)
__global__ __launch_bounds__(256) void fold_bo_part(
    const float* __restrict__ bd, const float* __restrict__ Wo,
    float* __restrict__ boP)
{
    const int n  = blockIdx.x * 256 + threadIdx.x;
    const int mb = blockIdx.y;
    float acc = 0.f;
    #pragma unroll 8
    for (int m = mb * 64; m < mb * 64 + 64; ++m)
        acc += bd[m & 127] * Wo[(size_t)m * DMODEL + n];
    boP[mb * DMODEL + n] = acc;
}

// fold_bo, stage 2: deterministic fixed-order reduction
__global__ __launch_bounds__(256) void fold_bo_reduce(
    const float* __restrict__ bo, const float* __restrict__ boP,
    float* __restrict__ boE)
{
    const int n = blockIdx.x * 256 + threadIdx.x;
    float acc = bo[n];
    #pragma unroll
    for (int i = 0; i < 32; ++i) acc += boP[i * DMODEL + n];
    boE[n] = acc;
}

// ---------------------------------------------------------------------------
// SGEMM: C[M,N] = A[M,K] @ B[K,N] + bias[N]
// 128x128 block tile, BK=16, 8x8 per thread, 256 threads, smem double buffer.
// ---------------------------------------------------------------------------
__global__ __launch_bounds__(256) void sgemm_bias(
    const float* __restrict__ A, const float* __restrict__ B,
    const float* __restrict__ bias, float* __restrict__ C,
    int M, int N, int K)
{
    __shared__ __align__(16) float As[2][16][132];
    __shared__ __align__(16) float Bs[2][16][128];

    const int tid = threadIdx.x;
    const int tx  = tid & 15;
    const int ty  = tid >> 4;
    const int m0  = blockIdx.y * 128;
    const int n0  = blockIdx.x * 128;

    const int aRow = tid >> 2;
    const int aCol = (tid & 3) * 4;
    const int bRow = tid >> 5;
    const int bCol = (tid & 31) * 4;

    const float* Aptr = A + (size_t)(m0 + aRow) * K + aCol;
    const float* Bptr = B + (size_t)bRow * N + n0 + bCol;

    float4 a0, a1, b0, b1;
    a0 = *(const float4*)(Aptr);
    a1 = *(const float4*)(Aptr + (size_t)64 * K);
    b0 = *(const float4*)(Bptr);
    b1 = *(const float4*)(Bptr + (size_t)8 * N);

    As[0][aCol + 0][aRow]      = a0.x;
    As[0][aCol + 1][aRow]      = a0.y;
    As[0][aCol + 2][aRow]      = a0.z;
    As[0][aCol + 3][aRow]      = a0.w;
    As[0][aCol + 0][aRow + 64] = a1.x;
    As[0][aCol + 1][aRow + 64] = a1.y;
    As[0][aCol + 2][aRow + 64] = a1.z;
    As[0][aCol + 3][aRow + 64] = a1.w;
    *(float4*)&Bs[0][bRow][bCol]     = b0;
    *(float4*)&Bs[0][bRow + 8][bCol] = b1;
    __syncthreads();

    float acc[8][8];
    #pragma unroll
    for (int i = 0; i < 8; ++i)
        #pragma unroll
        for (int j = 0; j < 8; ++j) acc[i][j] = 0.f;

    const int KT = K >> 4;
    for (int t = 0; t < KT; ++t) {
        const int cur = t & 1;
        if (t + 1 < KT) {
            const float* Ap = Aptr + (t + 1) * 16;
            const float* Bp = Bptr + (size_t)(t + 1) * 16 * N;
            a0 = *(const float4*)(Ap);
            a1 = *(const float4*)(Ap + (size_t)64 * K);
            b0 = *(const float4*)(Bp);
            b1 = *(const float4*)(Bp + (size_t)8 * N);
        }

        #pragma unroll
        for (int k = 0; k < 16; ++k) {
            float4 ra0 = *(const float4*)&As[cur][k][ty * 8];
            float4 ra1 = *(const float4*)&As[cur][k][ty * 8 + 4];
            float4 rb0 = *(const float4*)&Bs[cur][k][tx * 8];
            float4 rb1 = *(const float4*)&Bs[cur][k][tx * 8 + 4];
            float ar[8] = {ra0.x, ra0.y, ra0.z, ra0.w, ra1.x, ra1.y, ra1.z, ra1.w};
            float br[8] = {rb0.x, rb0.y, rb0.z, rb0.w, rb1.x, rb1.y, rb1.z, rb1.w};
            #pragma unroll
            for (int i = 0; i < 8; ++i)
                #pragma unroll
                for (int j = 0; j < 8; ++j)
                    acc[i][j] += ar[i] * br[j];
        }

        if (t + 1 < KT) {
            const int nxt = cur ^ 1;
            As[nxt][aCol + 0][aRow]      = a0.x;
            As[nxt][aCol + 1][aRow]      = a0.y;
            As[nxt][aCol + 2][aRow]      = a0.z;
            As[nxt][aCol + 3][aRow]      = a0.w;
            As[nxt][aCol + 0][aRow + 64] = a1.x;
            As[nxt][aCol + 1][aRow + 64] = a1.y;
            As[nxt][aCol + 2][aRow + 64] = a1.z;
            As[nxt][aCol + 3][aRow + 64] = a1.w;
            *(float4*)&Bs[nxt][bRow][bCol]     = b0;
            *(float4*)&Bs[nxt][bRow + 8][bCol] = b1;
        }
        __syncthreads();
    }

    const int row = m0 + ty * 8;
    const int col = n0 + tx * 8;
    float4 bv0 = *(const float4*)(bias + col);
    float4 bv1 = *(const float4*)(bias + col + 4);
    #pragma unroll
    for (int i = 0; i < 8; ++i) {
        float4 o0 = make_float4(acc[i][0] + bv0.x, acc[i][1] + bv0.y,
                                acc[i][2] + bv0.z, acc[i][3] + bv0.w);
        float4 o1 = make_float4(acc[i][4] + bv1.x, acc[i][5] + bv1.y,
                                acc[i][6] + bv1.z, acc[i][7] + bv1.w);
        *(float4*)(C + (size_t)(row + i) * N + col)     = o0;
        *(float4*)(C + (size_t)(row + i) * N + col + 4) = o1;
    }
}

// ---------------------------------------------------------------------------
// Compress (register-tiled): 64 (t,h)-rows x 32 cols per block, 128 threads,
// each thread computes 4x4 outputs. RoPE applied at smem load.
// Dynamic smem: rows[64][129] | Wcs[128][32] | bcs[32]  (~49.5 KB)
// ---------------------------------------------------------------------------
#define CMP_SMEM ((64 * 129 + 128 * 32 + 32) * 4)

__global__ __launch_bounds__(128) void compress_rope2(
    const float* __restrict__ X, const float* __restrict__ Wc,
    const float* __restrict__ bc, const float* __restrict__ cosT,
    const float* __restrict__ sinT, float* __restrict__ out)
{
    extern __shared__ float cs[];
    float (*rows)[129] = (float(*)[129])cs;            // 64*129
    float (*Wcs)[32]   = (float(*)[32])(cs + 64 * 129);
    float* bcs         = cs + 64 * 129 + 128 * 32;

    const int tid = threadIdx.x;
    const int r0  = blockIdx.x * 64;                   // first rid of block

    for (int i = tid; i < HDIM * LDIM; i += 128)
        Wcs[i >> 5][i & 31] = Wc[i];
    if (tid < 32) bcs[tid] = bc[tid];

    // Load 64 rows x 128 floats with RoPE. X offset = rid*128 + d (contiguous).
    #pragma unroll
    for (int i = 0; i < 16; ++i) {
        const int idx = tid + i * 128;                 // 0..2047
        const int r  = idx >> 5;                       // 0..63
        const int c4 = idx & 31;                       // float4 index 0..31
        const int rid = r0 + r;
        const int t = rid >> 4;
        const int l = t & (SEQ - 1);
        float4 v = *(const float4*)(X + (size_t)rid * HDIM + c4 * 4);
        float2 cc = *(const float2*)(cosT + l * 64 + c4 * 2);
        float2 ss = *(const float2*)(sinT + l * 64 + c4 * 2);
        float e0 = v.x, o0 = v.y, e1 = v.z, o1 = v.w;
        v.x = e0 * cc.x - o0 * ss.x;
        v.y = e0 * ss.x + o0 * cc.x;
        v.z = e1 * cc.y - o1 * ss.y;
        v.w = e1 * ss.y + o1 * cc.y;
        rows[r][c4 * 4 + 0] = v.x;
        rows[r][c4 * 4 + 1] = v.y;
        rows[r][c4 * 4 + 2] = v.z;
        rows[r][c4 * 4 + 3] = v.w;
    }
    __syncthreads();

    const int ty = tid >> 3;       // 0..15 -> rows ty*4..ty*4+3
    const int tx = tid & 7;        // 0..7  -> cols tx*4..tx*4+3
    float acc[4][4];
    #pragma unroll
    for (int i = 0; i < 4; ++i)
        #pragma unroll
        for (int j = 0; j < 4; ++j) acc[i][j] = 0.f;

    #pragma unroll 4
    for (int k = 0; k < HDIM; ++k) {
        float4 b = *(const float4*)&Wcs[k][tx * 4];
        float a0 = rows[ty * 4 + 0][k];
        float a1 = rows[ty * 4 + 1][k];
        float a2 = rows[ty * 4 + 2][k];
        float a3 = rows[ty * 4 + 3][k];
        acc[0][0] += a0 * b.x; acc[0][1] += a0 * b.y;
        acc[0][2] += a0 * b.z; acc[0][3] += a0 * b.w;
        acc[1][0] += a1 * b.x; acc[1][1] += a1 * b.y;
        acc[1][2] += a1 * b.z; acc[1][3] += a1 * b.w;
        acc[2][0] += a2 * b.x; acc[2][1] += a2 * b.y;
        acc[2][2] += a2 * b.z; acc[2][3] += a2 * b.w;
        acc[3][0] += a3 * b.x; acc[3][1] += a3 * b.y;
        acc[3][2] += a3 * b.z; acc[3][3] += a3 * b.w;
    }

    const float4 bb = *(const float4*)&bcs[tx * 4];
    #pragma unroll
    for (int i = 0; i < 4; ++i) {
        const int rid = r0 + ty * 4 + i;
        const int t = rid >> 4, h = rid & 15;
        const int l = t & (SEQ - 1);
        const int bh = (t >> 11) * NHEAD + h;
        float4 o;
        o.x = acc[i][0] + bb.x;
        o.y = acc[i][1] + bb.y;
        o.z = acc[i][2] + bb.z;
        o.w = acc[i][3] + bb.w;
        *(float4*)(out + ((size_t)bh * SEQ + l) * LDIM + tx * 4) = o;
    }
}

// ---------------------------------------------------------------------------
// Causal flash attention, head-dim 32, fp32, 2 queries per thread,
// 256-query tile, 8-key chunks, heavy-diagonal-first CTA order.
// Q/K in [bh, l, 32]; V and output in [t, h*32+e].
// ---------------------------------------------------------------------------
__global__ __launch_bounds__(128) void flash_kernel2(
    const float* __restrict__ QC, const float* __restrict__ KC,
    const float* __restrict__ VC2, float* __restrict__ AC2)
{
    __shared__ __align__(16) float kcs[128 * LDIM];
    __shared__ __align__(16) float vcs[128 * LDIM];

    const int tid = threadIdx.x;
    const int bh  = blockIdx.y;
    const int b   = bh >> 4, h = bh & 15;
    const int bx  = (int)gridDim.x - 1 - (int)blockIdx.x;   // heavy first
    const int q0  = bx * 256;
    const int qA  = q0 + tid;
    const int qB  = q0 + 128 + tid;
    const float scale = 0.17677669529663687f;   // 1/sqrt(32)

    const float* Vbase = VC2 + (size_t)b * SEQ * CDIM + h * LDIM;
    float*       Obase = AC2 + (size_t)b * SEQ * CDIM + h * LDIM;

    float qvA[LDIM], qvB[LDIM];
    {
        const float4* pa = (const float4*)(QC + ((size_t)bh * SEQ + qA) * LDIM);
        const float4* pb = (const float4*)(QC + ((size_t)bh * SEQ + qB) * LDIM);
        #pragma unroll
        for (int i = 0; i < 8; ++i) {
            float4 va = pa[i], vb = pb[i];
            qvA[i * 4 + 0] = va.x * scale; qvA[i * 4 + 1] = va.y * scale;
            qvA[i * 4 + 2] = va.z * scale; qvA[i * 4 + 3] = va.w * scale;
            qvB[i * 4 + 0] = vb.x * scale; qvB[i * 4 + 1] = vb.y * scale;
            qvB[i * 4 + 2] = vb.z * scale; qvB[i * 4 + 3] = vb.w * scale;
        }
    }

    float mA = -1e30f, lA = 0.f, mB = -1e30f, lB = 0.f;
    float accA[LDIM], accB[LDIM];
    #pragma unroll
    for (int e = 0; e < LDIM; ++e) { accA[e] = 0.f; accB[e] = 0.f; }

    const int ntiles = 2 * bx + 2;
    for (int kt = 0; kt < ntiles; ++kt) {
        const int kstart = kt * 128;
        const float4* kg = (const float4*)(KC + ((size_t)bh * SEQ + kstart) * LDIM);
        for (int idx = tid; idx < 128 * LDIM / 4; idx += 128) {
            ((float4*)kcs)[idx] = kg[idx];
            const int r = idx >> 3, j = idx & 7;
            ((float4*)vcs)[idx] =
                *(const float4*)(Vbase + (size_t)(kstart + r) * CDIM + j * 4);
        }
        __syncthreads();

        const bool doA   = (kt <= 2 * bx);       // uniform across block
        const bool maskA = (kt == 2 * bx);
        const bool maskB = (kt == 2 * bx + 1);

        #pragma unroll 1
        for (int c = 0; c < 16; ++c) {
            float svA[8], svB[8];
            #pragma unroll
            for (int kk = 0; kk < 8; ++kk) {
                const float4* kr = (const float4*)(kcs + (c * 8 + kk) * LDIM);
                float a0 = 0.f, a1 = 0.f, b0 = 0.f, b1 = 0.f;
                #pragma unroll
                for (int e4 = 0; e4 < 8; ++e4) {
                    float4 kv = kr[e4];
                    if (doA) {
                        a0 += qvA[e4 * 4 + 0] * kv.x + qvA[e4 * 4 + 1] * kv.y;
                        a1 += qvA[e4 * 4 + 2] * kv.z + qvA[e4 * 4 + 3] * kv.w;
                    }
                    b0 += qvB[e4 * 4 + 0] * kv.x + qvB[e4 * 4 + 1] * kv.y;
                    b1 += qvB[e4 * 4 + 2] * kv.z + qvB[e4 * 4 + 3] * kv.w;
                }
                svA[kk] = a0 + a1;
                svB[kk] = b0 + b1;
            }
            if (maskA) {
                #pragma unroll
                for (int kk = 0; kk < 8; ++kk)
                    if (kstart + c * 8 + kk > qA) svA[kk] = -1e30f;
            }
            if (maskB) {
                #pragma unroll
                for (int kk = 0; kk < 8; ++kk)
                    if (kstart + c * 8 + kk > qB) svB[kk] = -1e30f;
            }

            if (doA) {
                float cmax = svA[0];
                #pragma unroll
                for (int kk = 1; kk < 8; ++kk) cmax = fmaxf(cmax, svA[kk]);
                const float mnew = fmaxf(mA, cmax);
                const float r = __expf(mA - mnew);
                lA *= r;
                #pragma unroll
                for (int e = 0; e < LDIM; ++e) accA[e] *= r;
                #pragma unroll
                for (int kk = 0; kk < 8; ++kk)
                    svA[kk] = __expf(svA[kk] - mnew);
                #pragma unroll
                for (int kk = 0; kk < 8; ++kk) {
                    lA += svA[kk];
                    const float p = svA[kk];
                    const float4* vr = (const float4*)(vcs + (c * 8 + kk) * LDIM);
                    #pragma unroll
                    for (int e4 = 0; e4 < 8; ++e4) {
                        float4 vv = vr[e4];
                        accA[e4 * 4 + 0] += p * vv.x;
                        accA[e4 * 4 + 1] += p * vv.y;
                        accA[e4 * 4 + 2] += p * vv.z;
                        accA[e4 * 4 + 3] += p * vv.w;
                    }
                }
                mA = mnew;
            }
            {
                float cmax = svB[0];
                #pragma unroll
                for (int kk = 1; kk < 8; ++kk) cmax = fmaxf(cmax, svB[kk]);
                const float mnew = fmaxf(mB, cmax);
                const float r = __expf(mB - mnew);
                lB *= r;
                #pragma unroll
                for (int e = 0; e < LDIM; ++e) accB[e] *= r;
                #pragma unroll
                for (int kk = 0; kk < 8; ++kk)
                    svB[kk] = __expf(svB[kk] - mnew);
                #pragma unroll
                for (int kk = 0; kk < 8; ++kk) {
                    lB += svB[kk];
                    const float p = svB[kk];
                    const float4* vr = (const float4*)(vcs + (c * 8 + kk) * LDIM);
                    #pragma unroll
                    for (int e4 = 0; e4 < 8; ++e4) {
                        float4 vv = vr[e4];
                        accB[e4 * 4 + 0] += p * vv.x;
                        accB[e4 * 4 + 1] += p * vv.y;
                        accB[e4 * 4 + 2] += p * vv.z;
                        accB[e4 * 4 + 3] += p * vv.w;
                    }
                }
                mB = mnew;
            }
        }
        __syncthreads();
    }

    const float invA = 1.0f / lA;
    const float invB = 1.0f / lB;
    #pragma unroll
    for (int i = 0; i < 8; ++i) {
        float4 oa, ob;
        oa.x = accA[i * 4 + 0] * invA; oa.y = accA[i * 4 + 1] * invA;
        oa.z = accA[i * 4 + 2] * invA; oa.w = accA[i * 4 + 3] * invA;
        ob.x = accB[i * 4 + 0] * invB; ob.y = accB[i * 4 + 1] * invB;
        ob.z = accB[i * 4 + 2] * invB; ob.w = accB[i * 4 + 3] * invB;
        *(float4*)(Obase + (size_t)qA * CDIM + i * 4) = oa;
        *(float4*)(Obase + (size_t)qB * CDIM + i * 4) = ob;
    }
}

// ---------------------------------------------------------------------------
// Launch
// ---------------------------------------------------------------------------
extern "C" void kernel_launch(void* const* d_in, const int* in_sizes, int n_in,
                              void* d_out, int out_size)
{
    const float* x    = (const float*)d_in[0];
    const float* cosT = (const float*)d_in[1];
    const float* sinT = (const float*)d_in[2];
    const float* Wq   = (const float*)d_in[3];
    const float* bq   = (const float*)d_in[4];
    const float* Wk   = (const float*)d_in[5];
    const float* bk   = (const float*)d_in[6];
    const float* Wv   = (const float*)d_in[7];
    const float* bv   = (const float*)d_in[8];
    const float* Wqc  = (const float*)d_in[9];
    const float* bqc  = (const float*)d_in[10];
    const float* Wkc  = (const float*)d_in[11];
    const float* bkc  = (const float*)d_in[12];
    const float* Wvc  = (const float*)d_in[13];
    const float* bvc  = (const float*)d_in[14];
    const float* Wd   = (const float*)d_in[15];
    const float* bd   = (const float*)d_in[16];
    const float* Wo   = (const float*)d_in[17];
    const float* bo   = (const float*)d_in[18];
    float* out = (float*)d_out;

    float *Q, *Kb, *qc, *kc, *vc2, *ac2, *WvE, *WoE, *bvE, *boE, *boP;
    cudaGetSymbolAddress((void**)&Q,   g_Q);
    cudaGetSymbolAddress((void**)&Kb,  g_K);
    cudaGetSymbolAddress((void**)&qc,  g_qc);
    cudaGetSymbolAddress((void**)&kc,  g_kc);
    cudaGetSymbolAddress((void**)&vc2, g_vc2);
    cudaGetSymbolAddress((void**)&ac2, g_ac2);
    cudaGetSymbolAddress((void**)&WvE, g_WvE);
    cudaGetSymbolAddress((void**)&WoE, g_WoE);
    cudaGetSymbolAddress((void**)&bvE, g_bvE);
    cudaGetSymbolAddress((void**)&boE, g_boE);
    cudaGetSymbolAddress((void**)&boP, g_boP);

    cudaFuncSetAttribute(compress_rope2,
        cudaFuncAttributeMaxDynamicSharedMemorySize, CMP_SMEM);

    // Fold weights
    fold_v_kernel <<<dim3(NHEAD, DMODEL / 128), 256>>>(Wv, Wvc, WvE);
    fold_o_kernel <<<dim3(DMODEL / 128, NHEAD), 256>>>(Wd, Wo, WoE);
    fold_bv_kernel<<<2, 256>>>(bv, Wvc, bvc, bvE);
    fold_bo_part  <<<dim3(DMODEL / 256, 32), 256>>>(bd, Wo, boP);
    fold_bo_reduce<<<DMODEL / 256, 256>>>(bo, boP, boE);

    // Big GEMMs
    dim3 gg(DMODEL / 128, NTOK / 128);   // (16, 32)
    sgemm_bias<<<gg, 256>>>(x, Wq, bq, Q,  NTOK, DMODEL, DMODEL);
    sgemm_bias<<<gg, 256>>>(x, Wk, bk, Kb, NTOK, DMODEL, DMODEL);
    sgemm_bias<<<dim3(CDIM / 128, NTOK / 128), 256>>>(
        x, WvE, bvE, vc2, NTOK, CDIM, DMODEL);

    // RoPE + compression for Q, K (register-tiled)
    const int cblocks = (NTOK * NHEAD) / 64;   // 1024
    compress_rope2<<<cblocks, 128, CMP_SMEM>>>(Q,  Wqc, bqc, cosT, sinT, qc);
    compress_rope2<<<cblocks, 128, CMP_SMEM>>>(Kb, Wkc, bkc, cosT, sinT, kc);

    // Attention (2 queries/thread, single wave, heavy first)
    flash_kernel2<<<dim3(SEQ / 256, NBH), 128>>>(qc, kc, vc2, ac2);

    // Folded output GEMM
    sgemm_bias<<<gg, 256>>>(ac2, WoE, boE, out, NTOK, DMODEL, CDIM);
}

// round 16
// speedup vs baseline: 1.1915x; 1.1915x over previous
#include <cuda_runtime.h>
#include <cuda_bf16.h>

// ---------------------------------------------------------------------------
// CausalMLA — fp32, folded V/output paths (R12 baseline + fast fold_bo +
// heavy-diagonal-first flash ordering).
//   B=2, L=2048, D=2048, H=16, HD=128, LD=32
// ---------------------------------------------------------------------------

#define NTOK   4096
#define DMODEL 2048
#define NHEAD  16
#define HDIM   128
#define LDIM   32
#define SEQ    2048
#define NBH    32
#define CDIM   512      // NHEAD * LDIM

// Scratch (static device globals; no runtime allocation allowed)
__device__ float g_Q  [NTOK * DMODEL];
__device__ float g_K  [NTOK * DMODEL];
__device__ float g_qc [NBH * SEQ * LDIM];
__device__ float g_kc [NBH * SEQ * LDIM];
__device__ float g_vc2[NTOK * CDIM];     // [t, h*32+e]
__device__ float g_ac2[NTOK * CDIM];     // [t, h*32+e]
__device__ float g_WvE[DMODEL * CDIM];   // [d, h*32+e]
__device__ float g_WoE[CDIM * DMODEL];   // [h*32+e, n]
__device__ float g_bvE[CDIM];
__device__ float g_boE[DMODEL];
__device__ float g_boP[32 * DMODEL];     // partial sums for fold_bo

// ---------------------------------------------------------------------------
// Weight folding kernels
// ---------------------------------------------------------------------------
__global__ __launch_bounds__(256) void fold_v_kernel(
    const float* __restrict__ Wv, const float* __restrict__ Wvc,
    float* __restrict__ WvE)
{
    __shared__ float wc[HDIM * LDIM];
    const int tid = threadIdx.x;
    const int h   = blockIdx.x;
    const int d0  = blockIdx.y * 128;
    for (int i = tid; i < HDIM * LDIM; i += 256) wc[i] = Wvc[i];
    __syncthreads();

    #pragma unroll
    for (int i = 0; i < 16; ++i) {
        const int idx = tid + i * 256;
        const int r = idx >> 5, e = idx & 31;
        const float* wrow = Wv + (size_t)(d0 + r) * DMODEL + h * HDIM;
        float acc = 0.f;
        #pragma unroll 8
        for (int dd = 0; dd < HDIM; ++dd)
            acc += wrow[dd] * wc[dd * LDIM + e];
        WvE[(size_t)(d0 + r) * CDIM + h * LDIM + e] = acc;
    }
}

__global__ __launch_bounds__(256) void fold_o_kernel(
    const float* __restrict__ Wd, const float* __restrict__ Wo,
    float* __restrict__ WoE)
{
    __shared__ float wd[LDIM * HDIM];
    const int tid = threadIdx.x;
    const int n0  = blockIdx.x * 128;
    const int h   = blockIdx.y;
    for (int i = tid; i < LDIM * HDIM; i += 256) wd[i] = Wd[i];
    __syncthreads();

    #pragma unroll
    for (int i = 0; i < 16; ++i) {
        const int idx = tid + i * 256;
        const int e = idx >> 7, c = idx & 127;
        float acc = 0.f;
        #pragma unroll 8
        for (int d = 0; d < HDIM; ++d)
            acc += wd[e * HDIM + d] * Wo[(size_t)(h * HDIM + d) * DMODEL + n0 + c];
        WoE[(size_t)(h * LDIM + e) * DMODEL + n0 + c] = acc;
    }
}

__global__ __launch_bounds__(256) void fold_bv_kernel(
    const float* __restrict__ bv, const float* __restrict__ Wvc,
    const float* __restrict__ bvc, float* __restrict__ bvE)
{
    const int i = blockIdx.x * 256 + threadIdx.x;
    if (i >= CDIM) return;
    const int h = i >> 5, e = i & 31;
    float acc = bvc[e];
    for (int dd = 0; dd < HDIM; ++dd)
        acc += bv[h * HDIM + dd] * Wvc[dd * LDIM + e];
    bvE[i] = acc;
}

// fold_bo, stage 1: partial sums over 64-row m slabs (coalesced, 256 blocks)
__global__ __launch_bounds__(256) void fold_bo_part(
    const float* __restrict__ bd, const float* __restrict__ Wo,
    float* __restrict__ boP)
{
    const int n  = blockIdx.x * 256 + threadIdx.x;
    const int mb = blockIdx.y;
    float acc = 0.f;
    #pragma unroll 8
    for (int m = mb * 64; m < mb * 64 + 64; ++m)
        acc += bd[m & 127] * Wo[(size_t)m * DMODEL + n];
    boP[mb * DMODEL + n] = acc;
}

// fold_bo, stage 2: deterministic fixed-order reduction
__global__ __launch_bounds__(256) void fold_bo_reduce(
    const float* __restrict__ bo, const float* __restrict__ boP,
    float* __restrict__ boE)
{
    const int n = blockIdx.x * 256 + threadIdx.x;
    float acc = bo[n];
    #pragma unroll
    for (int i = 0; i < 32; ++i) acc += boP[i * DMODEL + n];
    boE[n] = acc;
}

// ---------------------------------------------------------------------------
// SGEMM: C[M,N] = A[M,K] @ B[K,N] + bias[N]
// 128x128 block tile, BK=16, 8x8 per thread, 256 threads, smem double buffer.
// ---------------------------------------------------------------------------
__global__ __launch_bounds__(256) void sgemm_bias(
    const float* __restrict__ A, const float* __restrict__ B,
    const float* __restrict__ bias, float* __restrict__ C,
    int M, int N, int K)
{
    __shared__ __align__(16) float As[2][16][132];
    __shared__ __align__(16) float Bs[2][16][128];

    const int tid = threadIdx.x;
    const int tx  = tid & 15;
    const int ty  = tid >> 4;
    const int m0  = blockIdx.y * 128;
    const int n0  = blockIdx.x * 128;

    const int aRow = tid >> 2;
    const int aCol = (tid & 3) * 4;
    const int bRow = tid >> 5;
    const int bCol = (tid & 31) * 4;

    const float* Aptr = A + (size_t)(m0 + aRow) * K + aCol;
    const float* Bptr = B + (size_t)bRow * N + n0 + bCol;

    float4 a0, a1, b0, b1;
    a0 = *(const float4*)(Aptr);
    a1 = *(const float4*)(Aptr + (size_t)64 * K);
    b0 = *(const float4*)(Bptr);
    b1 = *(const float4*)(Bptr + (size_t)8 * N);

    As[0][aCol + 0][aRow]      = a0.x;
    As[0][aCol + 1][aRow]      = a0.y;
    As[0][aCol + 2][aRow]      = a0.z;
    As[0][aCol + 3][aRow]      = a0.w;
    As[0][aCol + 0][aRow + 64] = a1.x;
    As[0][aCol + 1][aRow + 64] = a1.y;
    As[0][aCol + 2][aRow + 64] = a1.z;
    As[0][aCol + 3][aRow + 64] = a1.w;
    *(float4*)&Bs[0][bRow][bCol]     = b0;
    *(float4*)&Bs[0][bRow + 8][bCol] = b1;
    __syncthreads();

    float acc[8][8];
    #pragma unroll
    for (int i = 0; i < 8; ++i)
        #pragma unroll
        for (int j = 0; j < 8; ++j) acc[i][j] = 0.f;

    const int KT = K >> 4;
    for (int t = 0; t < KT; ++t) {
        const int cur = t & 1;
        if (t + 1 < KT) {
            const float* Ap = Aptr + (t + 1) * 16;
            const float* Bp = Bptr + (size_t)(t + 1) * 16 * N;
            a0 = *(const float4*)(Ap);
            a1 = *(const float4*)(Ap + (size_t)64 * K);
            b0 = *(const float4*)(Bp);
            b1 = *(const float4*)(Bp + (size_t)8 * N);
        }

        #pragma unroll
        for (int k = 0; k < 16; ++k) {
            float4 ra0 = *(const float4*)&As[cur][k][ty * 8];
            float4 ra1 = *(const float4*)&As[cur][k][ty * 8 + 4];
            float4 rb0 = *(const float4*)&Bs[cur][k][tx * 8];
            float4 rb1 = *(const float4*)&Bs[cur][k][tx * 8 + 4];
            float ar[8] = {ra0.x, ra0.y, ra0.z, ra0.w, ra1.x, ra1.y, ra1.z, ra1.w};
            float br[8] = {rb0.x, rb0.y, rb0.z, rb0.w, rb1.x, rb1.y, rb1.z, rb1.w};
            #pragma unroll
            for (int i = 0; i < 8; ++i)
                #pragma unroll
                for (int j = 0; j < 8; ++j)
                    acc[i][j] += ar[i] * br[j];
        }

        if (t + 1 < KT) {
            const int nxt = cur ^ 1;
            As[nxt][aCol + 0][aRow]      = a0.x;
            As[nxt][aCol + 1][aRow]      = a0.y;
            As[nxt][aCol + 2][aRow]      = a0.z;
            As[nxt][aCol + 3][aRow]      = a0.w;
            As[nxt][aCol + 0][aRow + 64] = a1.x;
            As[nxt][aCol + 1][aRow + 64] = a1.y;
            As[nxt][aCol + 2][aRow + 64] = a1.z;
            As[nxt][aCol + 3][aRow + 64] = a1.w;
            *(float4*)&Bs[nxt][bRow][bCol]     = b0;
            *(float4*)&Bs[nxt][bRow + 8][bCol] = b1;
        }
        __syncthreads();
    }

    const int row = m0 + ty * 8;
    const int col = n0 + tx * 8;
    float4 bv0 = *(const float4*)(bias + col);
    float4 bv1 = *(const float4*)(bias + col + 4);
    #pragma unroll
    for (int i = 0; i < 8; ++i) {
        float4 o0 = make_float4(acc[i][0] + bv0.x, acc[i][1] + bv0.y,
                                acc[i][2] + bv0.z, acc[i][3] + bv0.w);
        float4 o1 = make_float4(acc[i][4] + bv1.x, acc[i][5] + bv1.y,
                                acc[i][6] + bv1.z, acc[i][7] + bv1.w);
        *(float4*)(C + (size_t)(row + i) * N + col)     = o0;
        *(float4*)(C + (size_t)(row + i) * N + col + 4) = o1;
    }
}

// ---------------------------------------------------------------------------
// Compress: per (token, head) row of X[NTOK, DMODEL], apply RoPE,
// project 128 -> 32.  out[(bh*SEQ + l)*32 + e], bh = b*16 + h.
// ---------------------------------------------------------------------------
__global__ __launch_bounds__(256) void compress_rope_kernel(
    const float* __restrict__ X, const float* __restrict__ Wc,
    const float* __restrict__ bc, const float* __restrict__ cosT,
    const float* __restrict__ sinT, float* __restrict__ out)
{
    __shared__ float Wcs[HDIM * LDIM];
    __shared__ __align__(16) float rows[8][HDIM];

    const int tid  = threadIdx.x;
    const int lane = tid & 31;
    const int w    = tid >> 5;

    for (int i = tid; i < HDIM * LDIM; i += 256) Wcs[i] = Wc[i];
    __syncthreads();

    const int rid = blockIdx.x * 8 + w;
    const int t   = rid >> 4;
    const int h   = rid & 15;
    const int l   = t & (SEQ - 1);

    float4 v = *(const float4*)(X + (size_t)t * DMODEL + h * HDIM + lane * 4);
    {
        const float c0 = cosT[l * 64 + lane * 2];
        const float s0 = sinT[l * 64 + lane * 2];
        const float c1 = cosT[l * 64 + lane * 2 + 1];
        const float s1 = sinT[l * 64 + lane * 2 + 1];
        float e0 = v.x, o0 = v.y, e1 = v.z, o1 = v.w;
        v.x = e0 * c0 - o0 * s0;
        v.y = e0 * s0 + o0 * c0;
        v.z = e1 * c1 - o1 * s1;
        v.w = e1 * s1 + o1 * c1;
    }
    *(float4*)&rows[w][lane * 4] = v;
    __syncwarp();

    float acc = bc[lane];
    #pragma unroll
    for (int d = 0; d < HDIM; ++d)
        acc += rows[w][d] * Wcs[d * LDIM + lane];

    const int bh = (t >> 11) * NHEAD + h;
    out[((size_t)bh * SEQ + l) * LDIM + lane] = acc;
}

// ---------------------------------------------------------------------------
// Causal flash attention, head-dim 32, fp32, online softmax, 16-key chunks.
// Q/K in [bh, l, 32]; V and output in [t, h*32+e] (t = b*SEQ + l).
// Heavy-diagonal-first CTA ordering.
// ---------------------------------------------------------------------------
__global__ __launch_bounds__(128) void flash_kernel(
    const float* __restrict__ QC, const float* __restrict__ KC,
    const float* __restrict__ VC2, float* __restrict__ AC2)
{
    __shared__ __align__(16) float kcs[128 * LDIM];
    __shared__ __align__(16) float vcs[128 * LDIM];

    const int tid = threadIdx.x;
    const int bh  = blockIdx.y;
    const int b   = bh >> 4, h = bh & 15;
    const int bx  = (int)gridDim.x - 1 - (int)blockIdx.x;   // heavy first
    const int q0  = bx * 128;
    const int qi  = q0 + tid;
    const float scale = 0.17677669529663687f;   // 1/sqrt(32)

    const float* Vbase = VC2 + (size_t)b * SEQ * CDIM + h * LDIM;
    float*       Obase = AC2 + (size_t)b * SEQ * CDIM + h * LDIM;

    float qv[LDIM];
    {
        const float4* qp = (const float4*)(QC + ((size_t)bh * SEQ + qi) * LDIM);
        #pragma unroll
        for (int i = 0; i < 8; ++i) {
            float4 v = qp[i];
            qv[i * 4 + 0] = v.x * scale;
            qv[i * 4 + 1] = v.y * scale;
            qv[i * 4 + 2] = v.z * scale;
            qv[i * 4 + 3] = v.w * scale;
        }
    }

    float m = -1e30f, lsum = 0.f;
    float acc[LDIM];
    #pragma unroll
    for (int e = 0; e < LDIM; ++e) acc[e] = 0.f;

    const int ntiles = bx + 1;
    for (int kt = 0; kt < ntiles; ++kt) {
        const int kstart = kt * 128;
        const float4* kg = (const float4*)(KC + ((size_t)bh * SEQ + kstart) * LDIM);
        for (int idx = tid; idx < 128 * LDIM / 4; idx += 128) {
            ((float4*)kcs)[idx] = kg[idx];
            const int r = idx >> 3, j = idx & 7;
            ((float4*)vcs)[idx] =
                *(const float4*)(Vbase + (size_t)(kstart + r) * CDIM + j * 4);
        }
        __syncthreads();

        const bool masked = (kt == bx);

        #pragma unroll 1
        for (int c = 0; c < 8; ++c) {
            float sv[16];
            #pragma unroll
            for (int kk = 0; kk < 16; ++kk) {
                const float4* kr = (const float4*)(kcs + (c * 16 + kk) * LDIM);
                float d0 = 0.f, d1 = 0.f, d2 = 0.f, d3 = 0.f;
                #pragma unroll
                for (int e4 = 0; e4 < 8; ++e4) {
                    float4 kvv = kr[e4];
                    d0 += qv[e4 * 4 + 0] * kvv.x;
                    d1 += qv[e4 * 4 + 1] * kvv.y;
                    d2 += qv[e4 * 4 + 2] * kvv.z;
                    d3 += qv[e4 * 4 + 3] * kvv.w;
                }
                sv[kk] = (d0 + d1) + (d2 + d3);
            }
            if (masked) {
                #pragma unroll
                for (int kk = 0; kk < 16; ++kk)
                    if (kstart + c * 16 + kk > qi) sv[kk] = -1e30f;
            }
            float cmax = sv[0];
            #pragma unroll
            for (int kk = 1; kk < 16; ++kk) cmax = fmaxf(cmax, sv[kk]);
            const float mnew = fmaxf(m, cmax);
            const float r = __expf(m - mnew);
            lsum *= r;
            #pragma unroll
            for (int e = 0; e < LDIM; ++e) acc[e] *= r;
            #pragma unroll
            for (int kk = 0; kk < 16; ++kk) {
                const float p = __expf(sv[kk] - mnew);
                lsum += p;
                const float4* vr = (const float4*)(vcs + (c * 16 + kk) * LDIM);
                #pragma unroll
                for (int e4 = 0; e4 < 8; ++e4) {
                    float4 vv = vr[e4];
                    acc[e4 * 4 + 0] += p * vv.x;
                    acc[e4 * 4 + 1] += p * vv.y;
                    acc[e4 * 4 + 2] += p * vv.z;
                    acc[e4 * 4 + 3] += p * vv.w;
                }
            }
            m = mnew;
        }
        __syncthreads();
    }

    const float inv = 1.0f / lsum;
    #pragma unroll
    for (int i = 0; i < 8; ++i) {
        float4 o;
        o.x = acc[i * 4 + 0] * inv;
        o.y = acc[i * 4 + 1] * inv;
        o.z = acc[i * 4 + 2] * inv;
        o.w = acc[i * 4 + 3] * inv;
        *(float4*)(Obase + (size_t)qi * CDIM + i * 4) = o;
    }
}

// ---------------------------------------------------------------------------
// Launch
// ---------------------------------------------------------------------------
extern "C" void kernel_launch(void* const* d_in, const int* in_sizes, int n_in,
                              void* d_out, int out_size)
{
    const float* x    = (const float*)d_in[0];
    const float* cosT = (const float*)d_in[1];
    const float* sinT = (const float*)d_in[2];
    const float* Wq   = (const float*)d_in[3];
    const float* bq   = (const float*)d_in[4];
    const float* Wk   = (const float*)d_in[5];
    const float* bk   = (const float*)d_in[6];
    const float* Wv   = (const float*)d_in[7];
    const float* bv   = (const float*)d_in[8];
    const float* Wqc  = (const float*)d_in[9];
    const float* bqc  = (const float*)d_in[10];
    const float* Wkc  = (const float*)d_in[11];
    const float* bkc  = (const float*)d_in[12];
    const float* Wvc  = (const float*)d_in[13];
    const float* bvc  = (const float*)d_in[14];
    const float* Wd   = (const float*)d_in[15];
    const float* bd   = (const float*)d_in[16];
    const float* Wo   = (const float*)d_in[17];
    const float* bo   = (const float*)d_in[18];
    float* out = (float*)d_out;

    float *Q, *Kb, *qc, *kc, *vc2, *ac2, *WvE, *WoE, *bvE, *boE, *boP;
    cudaGetSymbolAddress((void**)&Q,   g_Q);
    cudaGetSymbolAddress((void**)&Kb,  g_K);
    cudaGetSymbolAddress((void**)&qc,  g_qc);
    cudaGetSymbolAddress((void**)&kc,  g_kc);
    cudaGetSymbolAddress((void**)&vc2, g_vc2);
    cudaGetSymbolAddress((void**)&ac2, g_ac2);
    cudaGetSymbolAddress((void**)&WvE, g_WvE);
    cudaGetSymbolAddress((void**)&WoE, g_WoE);
    cudaGetSymbolAddress((void**)&bvE, g_bvE);
    cudaGetSymbolAddress((void**)&boE, g_boE);
    cudaGetSymbolAddress((void**)&boP, g_boP);

    // Fold weights
    fold_v_kernel <<<dim3(NHEAD, DMODEL / 128), 256>>>(Wv, Wvc, WvE);
    fold_o_kernel <<<dim3(DMODEL / 128, NHEAD), 256>>>(Wd, Wo, WoE);
    fold_bv_kernel<<<2, 256>>>(bv, Wvc, bvc, bvE);
    fold_bo_part  <<<dim3(DMODEL / 256, 32), 256>>>(bd, Wo, boP);
    fold_bo_reduce<<<DMODEL / 256, 256>>>(bo, boP, boE);

    // Big GEMMs
    dim3 gg(DMODEL / 128, NTOK / 128);   // (16, 32)
    sgemm_bias<<<gg, 256>>>(x, Wq, bq, Q,  NTOK, DMODEL, DMODEL);
    sgemm_bias<<<gg, 256>>>(x, Wk, bk, Kb, NTOK, DMODEL, DMODEL);
    sgemm_bias<<<dim3(CDIM / 128, NTOK / 128), 256>>>(
        x, WvE, bvE, vc2, NTOK, CDIM, DMODEL);

    // RoPE + compression for Q, K
    const int nblocks = (NTOK * NHEAD) / 8;   // 8192
    compress_rope_kernel<<<nblocks, 256>>>(Q,  Wqc, bqc, cosT, sinT, qc);
    compress_rope_kernel<<<nblocks, 256>>>(Kb, Wkc, bkc, cosT, sinT, kc);

    // Attention (heavy-diagonal-first)
    flash_kernel<<<dim3(SEQ / 128, NBH), 128>>>(qc, kc, vc2, ac2);

    // Folded output GEMM
    sgemm_bias<<<gg, 256>>>(ac2, WoE, boE, out, NTOK, DMODEL, CDIM);
}

// round 17
// speedup vs baseline: 1.8961x; 1.5914x over previous
#include <cuda_runtime.h>
#include <cuda_bf16.h>
#include <cstdint>

// ---------------------------------------------------------------------------
// CausalMLA — mma.sync tf32 GEMMs + fp32 attention, folded V/output paths
//   B=2, L=2048, D=2048, H=16, HD=128, LD=32
// ---------------------------------------------------------------------------

#define NTOK   4096
#define DMODEL 2048
#define NHEAD  16
#define HDIM   128
#define LDIM   32
#define SEQ    2048
#define NBH    32
#define CDIM   512      // NHEAD * LDIM

// Scratch (static device globals; no runtime allocation allowed)
__device__ float g_Q  [NTOK * DMODEL];
__device__ float g_K  [NTOK * DMODEL];
__device__ float g_qc [NBH * SEQ * LDIM];
__device__ float g_kc [NBH * SEQ * LDIM];
__device__ float g_vc2[NTOK * CDIM];     // [t, h*32+e]
__device__ float g_ac2[NTOK * CDIM];     // [t, h*32+e]
__device__ float g_WvE[DMODEL * CDIM];   // [d, h*32+e]
__device__ float g_WoE[CDIM * DMODEL];   // [h*32+e, n]
__device__ float g_bvE[CDIM];
__device__ float g_boE[DMODEL];
__device__ float g_boP[32 * DMODEL];     // partial sums for fold_bo

__device__ __forceinline__ float to_tf32(float x) {
    float r;
    asm("cvt.rna.tf32.f32 %0, %1;" : "=f"(r) : "f"(x));
    return r;
}

// ---------------------------------------------------------------------------
// Weight folding kernels
// ---------------------------------------------------------------------------
__global__ __launch_bounds__(256) void fold_v_kernel(
    const float* __restrict__ Wv, const float* __restrict__ Wvc,
    float* __restrict__ WvE)
{
    __shared__ float wc[HDIM * LDIM];
    const int tid = threadIdx.x;
    const int h   = blockIdx.x;
    const int d0  = blockIdx.y * 128;
    for (int i = tid; i < HDIM * LDIM; i += 256) wc[i] = Wvc[i];
    __syncthreads();

    #pragma unroll
    for (int i = 0; i < 16; ++i) {
        const int idx = tid + i * 256;
        const int r = idx >> 5, e = idx & 31;
        const float* wrow = Wv + (size_t)(d0 + r) * DMODEL + h * HDIM;
        float acc = 0.f;
        #pragma unroll 8
        for (int dd = 0; dd < HDIM; ++dd)
            acc += wrow[dd] * wc[dd * LDIM + e];
        WvE[(size_t)(d0 + r) * CDIM + h * LDIM + e] = acc;
    }
}

__global__ __launch_bounds__(256) void fold_o_kernel(
    const float* __restrict__ Wd, const float* __restrict__ Wo,
    float* __restrict__ WoE)
{
    __shared__ float wd[LDIM * HDIM];
    const int tid = threadIdx.x;
    const int n0  = blockIdx.x * 128;
    const int h   = blockIdx.y;
    for (int i = tid; i < LDIM * HDIM; i += 256) wd[i] = Wd[i];
    __syncthreads();

    #pragma unroll
    for (int i = 0; i < 16; ++i) {
        const int idx = tid + i * 256;
        const int e = idx >> 7, c = idx & 127;
        float acc = 0.f;
        #pragma unroll 8
        for (int d = 0; d < HDIM; ++d)
            acc += wd[e * HDIM + d] * Wo[(size_t)(h * HDIM + d) * DMODEL + n0 + c];
        WoE[(size_t)(h * LDIM + e) * DMODEL + n0 + c] = acc;
    }
}

__global__ __launch_bounds__(256) void fold_bv_kernel(
    const float* __restrict__ bv, const float* __restrict__ Wvc,
    const float* __restrict__ bvc, float* __restrict__ bvE)
{
    const int i = blockIdx.x * 256 + threadIdx.x;
    if (i >= CDIM) return;
    const int h = i >> 5, e = i & 31;
    float acc = bvc[e];
    for (int dd = 0; dd < HDIM; ++dd)
        acc += bv[h * HDIM + dd] * Wvc[dd * LDIM + e];
    bvE[i] = acc;
}

__global__ __launch_bounds__(256) void fold_bo_part(
    const float* __restrict__ bd, const float* __restrict__ Wo,
    float* __restrict__ boP)
{
    const int n  = blockIdx.x * 256 + threadIdx.x;
    const int mb = blockIdx.y;
    float acc = 0.f;
    #pragma unroll 8
    for (int m = mb * 64; m < mb * 64 + 64; ++m)
        acc += bd[m & 127] * Wo[(size_t)m * DMODEL + n];
    boP[mb * DMODEL + n] = acc;
}

__global__ __launch_bounds__(256) void fold_bo_reduce(
    const float* __restrict__ bo, const float* __restrict__ boP,
    float* __restrict__ boE)
{
    const int n = blockIdx.x * 256 + threadIdx.x;
    float acc = bo[n];
    #pragma unroll
    for (int i = 0; i < 32; ++i) acc += boP[i * DMODEL + n];
    boE[n] = acc;
}

// ---------------------------------------------------------------------------
// mma.sync tf32 GEMM: C[M,N] = A[M,K] @ B[K,N] + bias[N]
// 128x128 CTA tile, BK=32, 256 threads / 8 warps (2x4), warp tile 64x32.
// mma.sync.aligned.m16n8k8.row.col.f32.tf32.tf32.f32
// smem: As[2][32][136] ([k][m], 136-stride = conflict-free fragment loads),
//       Bs[2][32][136] ([k][n]).  Double-buffered, tf32 cvt in loader.
// ---------------------------------------------------------------------------
#define GSTRIDE 136
#define GEMM_SMEM (4 * 32 * GSTRIDE * 4)   // 69632 B

__global__ __launch_bounds__(256, 1) void sgemm_mma(
    const float* __restrict__ A, const float* __restrict__ B,
    const float* __restrict__ bias, float* __restrict__ C,
    int M, int N, int K)
{
    extern __shared__ __align__(16) float sm[];
    float* sA = sm;                      // [2][32][GSTRIDE]
    float* sB = sm + 2 * 32 * GSTRIDE;   // [2][32][GSTRIDE]

    const int tid  = threadIdx.x;
    const int wid  = tid >> 5;
    const int lane = tid & 31;
    const int g    = lane >> 2;          // 0..7
    const int q    = lane & 3;           // 0..3
    const int wr   = wid >> 2;           // 0..1 -> 64-row slab
    const int wc   = wid & 3;            // 0..3 -> 32-col slab
    const int m0   = blockIdx.y * 128;
    const int n0   = blockIdx.x * 128;
    const int mW   = wr * 64;
    const int nW   = wc * 32;

    // loader indices
    const int aR = tid >> 2;             // 0..63 (+64 second slab)
    const int aC = (tid & 3) * 8;        // 0,8,16,24
    const int bR = tid >> 3;             // 0..31
    const int bC = (tid & 7) * 16;       // 0..112

    const float* Ap = A + (size_t)(m0 + aR) * K + aC;
    const float* Bp = B + (size_t)bR * N + n0 + bC;

    float4 pa[4], pb[4];

    auto fetch = [&](int t) {
        const float* a = Ap + t * 32;
        const float* b = Bp + (size_t)t * 32 * N;
        pa[0] = *(const float4*)(a);
        pa[1] = *(const float4*)(a + 4);
        pa[2] = *(const float4*)(a + (size_t)64 * K);
        pa[3] = *(const float4*)(a + (size_t)64 * K + 4);
        pb[0] = *(const float4*)(b);
        pb[1] = *(const float4*)(b + 4);
        pb[2] = *(const float4*)(b + 8);
        pb[3] = *(const float4*)(b + 12);
    };
    auto stage = [&](int buf) {
        float* As = sA + buf * 32 * GSTRIDE;
        float* Bs = sB + buf * 32 * GSTRIDE;
        #pragma unroll
        for (int s = 0; s < 2; ++s) {
            const int r = aR + s * 64;
            float4 v0 = pa[s * 2], v1 = pa[s * 2 + 1];
            As[(aC + 0) * GSTRIDE + r] = to_tf32(v0.x);
            As[(aC + 1) * GSTRIDE + r] = to_tf32(v0.y);
            As[(aC + 2) * GSTRIDE + r] = to_tf32(v0.z);
            As[(aC + 3) * GSTRIDE + r] = to_tf32(v0.w);
            As[(aC + 4) * GSTRIDE + r] = to_tf32(v1.x);
            As[(aC + 5) * GSTRIDE + r] = to_tf32(v1.y);
            As[(aC + 6) * GSTRIDE + r] = to_tf32(v1.z);
            As[(aC + 7) * GSTRIDE + r] = to_tf32(v1.w);
        }
        #pragma unroll
        for (int s = 0; s < 4; ++s) {
            float4 v = pb[s];
            v.x = to_tf32(v.x); v.y = to_tf32(v.y);
            v.z = to_tf32(v.z); v.w = to_tf32(v.w);
            *(float4*)&Bs[bR * GSTRIDE + bC + s * 4] = v;
        }
    };

    fetch(0);
    stage(0);
    __syncthreads();

    float c[4][4][4];   // [mt][nt][frag]
    #pragma unroll
    for (int i = 0; i < 4; ++i)
        #pragma unroll
        for (int j = 0; j < 4; ++j)
            #pragma unroll
            for (int e = 0; e < 4; ++e) c[i][j][e] = 0.f;

    const int KT = K >> 5;
    for (int t = 0; t < KT; ++t) {
        const int cur = t & 1;
        if (t + 1 < KT) fetch(t + 1);

        const float* As = sA + cur * 32 * GSTRIDE;
        const float* Bs = sB + cur * 32 * GSTRIDE;

        #pragma unroll
        for (int ks = 0; ks < 4; ++ks) {
            const int k0 = ks * 8;
            uint32_t af[4][4], bf[4][2];
            #pragma unroll
            for (int mt = 0; mt < 4; ++mt) {
                const int mb = mW + mt * 16 + g;
                af[mt][0] = __float_as_uint(As[(k0 + q)     * GSTRIDE + mb]);
                af[mt][1] = __float_as_uint(As[(k0 + q)     * GSTRIDE + mb + 8]);
                af[mt][2] = __float_as_uint(As[(k0 + q + 4) * GSTRIDE + mb]);
                af[mt][3] = __float_as_uint(As[(k0 + q + 4) * GSTRIDE + mb + 8]);
            }
            #pragma unroll
            for (int nt = 0; nt < 4; ++nt) {
                const int nb = nW + nt * 8 + g;
                bf[nt][0] = __float_as_uint(Bs[(k0 + q)     * GSTRIDE + nb]);
                bf[nt][1] = __float_as_uint(Bs[(k0 + q + 4) * GSTRIDE + nb]);
            }
            #pragma unroll
            for (int mt = 0; mt < 4; ++mt)
                #pragma unroll
                for (int nt = 0; nt < 4; ++nt) {
                    asm volatile(
                        "mma.sync.aligned.m16n8k8.row.col.f32.tf32.tf32.f32 "
                        "{%0,%1,%2,%3}, {%4,%5,%6,%7}, {%8,%9}, {%0,%1,%2,%3};"
                        : "+f"(c[mt][nt][0]), "+f"(c[mt][nt][1]),
                          "+f"(c[mt][nt][2]), "+f"(c[mt][nt][3])
                        : "r"(af[mt][0]), "r"(af[mt][1]),
                          "r"(af[mt][2]), "r"(af[mt][3]),
                          "r"(bf[nt][0]), "r"(bf[nt][1]));
                }
        }

        if (t + 1 < KT) stage(cur ^ 1);
        __syncthreads();
    }

    // Epilogue: c0:(g,2q) c1:(g,2q+1) c2:(g+8,2q) c3:(g+8,2q+1)
    #pragma unroll
    for (int nt = 0; nt < 4; ++nt) {
        const int col = n0 + nW + nt * 8 + 2 * q;
        const float2 bb = *(const float2*)(bias + col);
        #pragma unroll
        for (int mt = 0; mt < 4; ++mt) {
            const int r0 = m0 + mW + mt * 16 + g;
            float2 o0 = make_float2(c[mt][nt][0] + bb.x, c[mt][nt][1] + bb.y);
            float2 o1 = make_float2(c[mt][nt][2] + bb.x, c[mt][nt][3] + bb.y);
            *(float2*)(C + (size_t)r0 * N + col)       = o0;
            *(float2*)(C + (size_t)(r0 + 8) * N + col) = o1;
        }
    }
}

// ---------------------------------------------------------------------------
// Compress: per (token, head) row of X[NTOK, DMODEL], apply RoPE,
// project 128 -> 32.  out[(bh*SEQ + l)*32 + e], bh = b*16 + h.
// ---------------------------------------------------------------------------
__global__ __launch_bounds__(256) void compress_rope_kernel(
    const float* __restrict__ X, const float* __restrict__ Wc,
    const float* __restrict__ bc, const float* __restrict__ cosT,
    const float* __restrict__ sinT, float* __restrict__ out)
{
    __shared__ float Wcs[HDIM * LDIM];
    __shared__ __align__(16) float rows[8][HDIM];

    const int tid  = threadIdx.x;
    const int lane = tid & 31;
    const int w    = tid >> 5;

    for (int i = tid; i < HDIM * LDIM; i += 256) Wcs[i] = Wc[i];
    __syncthreads();

    const int rid = blockIdx.x * 8 + w;
    const int t   = rid >> 4;
    const int h   = rid & 15;
    const int l   = t & (SEQ - 1);

    float4 v = *(const float4*)(X + (size_t)t * DMODEL + h * HDIM + lane * 4);
    {
        const float c0 = cosT[l * 64 + lane * 2];
        const float s0 = sinT[l * 64 + lane * 2];
        const float c1 = cosT[l * 64 + lane * 2 + 1];
        const float s1 = sinT[l * 64 + lane * 2 + 1];
        float e0 = v.x, o0 = v.y, e1 = v.z, o1 = v.w;
        v.x = e0 * c0 - o0 * s0;
        v.y = e0 * s0 + o0 * c0;
        v.z = e1 * c1 - o1 * s1;
        v.w = e1 * s1 + o1 * c1;
    }
    *(float4*)&rows[w][lane * 4] = v;
    __syncwarp();

    float acc = bc[lane];
    #pragma unroll
    for (int d = 0; d < HDIM; ++d)
        acc += rows[w][d] * Wcs[d * LDIM + lane];

    const int bh = (t >> 11) * NHEAD + h;
    out[((size_t)bh * SEQ + l) * LDIM + lane] = acc;
}

// ---------------------------------------------------------------------------
// Causal flash attention, head-dim 32, fp32, online softmax, 16-key chunks.
// Q/K in [bh, l, 32]; V and output in [t, h*32+e] (t = b*SEQ + l).
// ---------------------------------------------------------------------------
__global__ __launch_bounds__(128) void flash_kernel(
    const float* __restrict__ QC, const float* __restrict__ KC,
    const float* __restrict__ VC2, float* __restrict__ AC2)
{
    __shared__ __align__(16) float kcs[128 * LDIM];
    __shared__ __align__(16) float vcs[128 * LDIM];

    const int tid = threadIdx.x;
    const int bh  = blockIdx.y;
    const int b   = bh >> 4, h = bh & 15;
    const int q0  = blockIdx.x * 128;
    const int qi  = q0 + tid;
    const float scale = 0.17677669529663687f;   // 1/sqrt(32)

    const float* Vbase = VC2 + (size_t)b * SEQ * CDIM + h * LDIM;
    float*       Obase = AC2 + (size_t)b * SEQ * CDIM + h * LDIM;

    float qv[LDIM];
    {
        const float4* qp = (const float4*)(QC + ((size_t)bh * SEQ + qi) * LDIM);
        #pragma unroll
        for (int i = 0; i < 8; ++i) {
            float4 v = qp[i];
            qv[i * 4 + 0] = v.x * scale;
            qv[i * 4 + 1] = v.y * scale;
            qv[i * 4 + 2] = v.z * scale;
            qv[i * 4 + 3] = v.w * scale;
        }
    }

    float m = -1e30f, lsum = 0.f;
    float acc[LDIM];
    #pragma unroll
    for (int e = 0; e < LDIM; ++e) acc[e] = 0.f;

    const int ntiles = blockIdx.x + 1;
    for (int kt = 0; kt < ntiles; ++kt) {
        const int kstart = kt * 128;
        const float4* kg = (const float4*)(KC + ((size_t)bh * SEQ + kstart) * LDIM);
        for (int idx = tid; idx < 128 * LDIM / 4; idx += 128) {
            ((float4*)kcs)[idx] = kg[idx];
            const int r = idx >> 3, j = idx & 7;
            ((float4*)vcs)[idx] =
                *(const float4*)(Vbase + (size_t)(kstart + r) * CDIM + j * 4);
        }
        __syncthreads();

        const bool masked = (kt == blockIdx.x);

        #pragma unroll 1
        for (int c = 0; c < 8; ++c) {
            float sv[16];
            #pragma unroll
            for (int kk = 0; kk < 16; ++kk) {
                const float4* kr = (const float4*)(kcs + (c * 16 + kk) * LDIM);
                float d0 = 0.f, d1 = 0.f, d2 = 0.f, d3 = 0.f;
                #pragma unroll
                for (int e4 = 0; e4 < 8; ++e4) {
                    float4 kvv = kr[e4];
                    d0 += qv[e4 * 4 + 0] * kvv.x;
                    d1 += qv[e4 * 4 + 1] * kvv.y;
                    d2 += qv[e4 * 4 + 2] * kvv.z;
                    d3 += qv[e4 * 4 + 3] * kvv.w;
                }
                sv[kk] = (d0 + d1) + (d2 + d3);
            }
            if (masked) {
                #pragma unroll
                for (int kk = 0; kk < 16; ++kk)
                    if (kstart + c * 16 + kk > qi) sv[kk] = -1e30f;
            }
            float cmax = sv[0];
            #pragma unroll
            for (int kk = 1; kk < 16; ++kk) cmax = fmaxf(cmax, sv[kk]);
            const float mnew = fmaxf(m, cmax);
            const float r = __expf(m - mnew);
            lsum *= r;
            #pragma unroll
            for (int e = 0; e < LDIM; ++e) acc[e] *= r;
            #pragma unroll
            for (int kk = 0; kk < 16; ++kk) {
                const float p = __expf(sv[kk] - mnew);
                lsum += p;
                const float4* vr = (const float4*)(vcs + (c * 16 + kk) * LDIM);
                #pragma unroll
                for (int e4 = 0; e4 < 8; ++e4) {
                    float4 vv = vr[e4];
                    acc[e4 * 4 + 0] += p * vv.x;
                    acc[e4 * 4 + 1] += p * vv.y;
                    acc[e4 * 4 + 2] += p * vv.z;
                    acc[e4 * 4 + 3] += p * vv.w;
                }
            }
            m = mnew;
        }
        __syncthreads();
    }

    const float inv = 1.0f / lsum;
    #pragma unroll
    for (int i = 0; i < 8; ++i) {
        float4 o;
        o.x = acc[i * 4 + 0] * inv;
        o.y = acc[i * 4 + 1] * inv;
        o.z = acc[i * 4 + 2] * inv;
        o.w = acc[i * 4 + 3] * inv;
        *(float4*)(Obase + (size_t)qi * CDIM + i * 4) = o;
    }
}

// ---------------------------------------------------------------------------
// Launch
// ---------------------------------------------------------------------------
extern "C" void kernel_launch(void* const* d_in, const int* in_sizes, int n_in,
                              void* d_out, int out_size)
{
    const float* x    = (const float*)d_in[0];
    const float* cosT = (const float*)d_in[1];
    const float* sinT = (const float*)d_in[2];
    const float* Wq   = (const float*)d_in[3];
    const float* bq   = (const float*)d_in[4];
    const float* Wk   = (const float*)d_in[5];
    const float* bk   = (const float*)d_in[6];
    const float* Wv   = (const float*)d_in[7];
    const float* bv   = (const float*)d_in[8];
    const float* Wqc  = (const float*)d_in[9];
    const float* bqc  = (const float*)d_in[10];
    const float* Wkc  = (const float*)d_in[11];
    const float* bkc  = (const float*)d_in[12];
    const float* Wvc  = (const float*)d_in[13];
    const float* bvc  = (const float*)d_in[14];
    const float* Wd   = (const float*)d_in[15];
    const float* bd   = (const float*)d_in[16];
    const float* Wo   = (const float*)d_in[17];
    const float* bo   = (const float*)d_in[18];
    float* out = (float*)d_out;

    float *Q, *Kb, *qc, *kc, *vc2, *ac2, *WvE, *WoE, *bvE, *boE, *boP;
    cudaGetSymbolAddress((void**)&Q,   g_Q);
    cudaGetSymbolAddress((void**)&Kb,  g_K);
    cudaGetSymbolAddress((void**)&qc,  g_qc);
    cudaGetSymbolAddress((void**)&kc,  g_kc);
    cudaGetSymbolAddress((void**)&vc2, g_vc2);
    cudaGetSymbolAddress((void**)&ac2, g_ac2);
    cudaGetSymbolAddress((void**)&WvE, g_WvE);
    cudaGetSymbolAddress((void**)&WoE, g_WoE);
    cudaGetSymbolAddress((void**)&bvE, g_bvE);
    cudaGetSymbolAddress((void**)&boE, g_boE);
    cudaGetSymbolAddress((void**)&boP, g_boP);

    cudaFuncSetAttribute(sgemm_mma,
        cudaFuncAttributeMaxDynamicSharedMemorySize, GEMM_SMEM);

    // Fold weights
    fold_v_kernel <<<dim3(NHEAD, DMODEL / 128), 256>>>(Wv, Wvc, WvE);
    fold_o_kernel <<<dim3(DMODEL / 128, NHEAD), 256>>>(Wd, Wo, WoE);
    fold_bv_kernel<<<2, 256>>>(bv, Wvc, bvc, bvE);
    fold_bo_part  <<<dim3(DMODEL / 256, 32), 256>>>(bd, Wo, boP);
    fold_bo_reduce<<<DMODEL / 256, 256>>>(bo, boP, boE);

    // Big GEMMs (tensor path)
    dim3 gg(DMODEL / 128, NTOK / 128);   // (16, 32)
    sgemm_mma<<<gg, 256, GEMM_SMEM>>>(x, Wq, bq, Q,  NTOK, DMODEL, DMODEL);
    sgemm_mma<<<gg, 256, GEMM_SMEM>>>(x, Wk, bk, Kb, NTOK, DMODEL, DMODEL);
    sgemm_mma<<<dim3(CDIM / 128, NTOK / 128), 256, GEMM_SMEM>>>(
        x, WvE, bvE, vc2, NTOK, CDIM, DMODEL);

    // RoPE + compression for Q, K
    const int nblocks = (NTOK * NHEAD) / 8;   // 8192
    compress_rope_kernel<<<nblocks, 256>>>(Q,  Wqc, bqc, cosT, sinT, qc);
    compress_rope_kernel<<<nblocks, 256>>>(Kb, Wkc, bkc, cosT, sinT, kc);

    // Attention
    flash_kernel<<<dim3(SEQ / 128, NBH), 128>>>(qc, kc, vc2, ac2);

    // Folded output GEMM
    sgemm_mma<<<gg, 256, GEMM_SMEM>>>(ac2, WoE, boE, out, NTOK, DMODEL, CDIM);
}